// round 10
// baseline (speedup 1.0000x reference)
#include <cuda_runtime.h>
#include <cuda_fp16.h>
#include <cstdint>
#include <cstring>

#define NN 8192
#define DIM 128
#define KCHUNK 64
#define QITER 32                       // chunks per quarter (2048/64)
#define MTILE 64
#define TPB 512
#define TILE_STRIDE_H 136              // halves per k-row (128 + 8 pad) -> 272 B
#define TILE_BYTES (KCHUNK * TILE_STRIDE_H * 2)   // 17408
#define RING_STAGES 3
#define RING_BYTES (RING_STAGES * TILE_BYTES)     // 52224
#define SMEM_TOTAL (4 * RING_BYTES)    // 208896

__device__ float2 g_W2[NN];            // (exp(s2), exp(0.2 s2))
__device__ float2 g_E1F1[NN];          // 0.0625 * (exp(s1), exp(0.2 s1))
__device__ __align__(16) __half g_Bt[(NN / KCHUNK) * KCHUNK * TILE_STRIDE_H];

// ---------------- helpers ----------------
__device__ __forceinline__ uint32_t smem_u32(const void* p) {
    uint32_t r;
    asm("{ .reg .u64 t; cvta.to.shared.u64 t, %1; cvt.u32.u64 %0, t; }" : "=r"(r) : "l"(p));
    return r;
}
__device__ __forceinline__ void cp16(uint32_t d, const void* s) {
    asm volatile("cp.async.cg.shared.global [%0], [%1], 16;" :: "r"(d), "l"(s) : "memory");
}
#define CP_COMMIT() asm volatile("cp.async.commit_group;" ::: "memory")
#define CP_WAIT1() asm volatile("cp.async.wait_group 1;" ::: "memory")
#define CP_WAIT0() asm volatile("cp.async.wait_group 0;" ::: "memory")

__device__ __forceinline__ void ldm4t(uint32_t& r0, uint32_t& r1, uint32_t& r2, uint32_t& r3, uint32_t a) {
    asm volatile("ldmatrix.sync.aligned.m8n8.x4.trans.shared.b16 {%0,%1,%2,%3}, [%4];"
        : "=r"(r0), "=r"(r1), "=r"(r2), "=r"(r3) : "r"(a));
}
__device__ __forceinline__ void mma16816(float* d, const uint32_t* a, uint32_t b0, uint32_t b1) {
    asm volatile("mma.sync.aligned.m16n8k16.row.col.f32.f16.f16.f32 "
        "{%0,%1,%2,%3},{%4,%5,%6,%7},{%8,%9},{%0,%1,%2,%3};"
        : "+f"(d[0]), "+f"(d[1]), "+f"(d[2]), "+f"(d[3])
        : "r"(a[0]), "r"(a[1]), "r"(a[2]), "r"(a[3]), "r"(b0), "r"(b1));
}
__device__ __forceinline__ uint32_t pack_h2(float a, float b) {
    __half2 h = __floats2half2_rn(a, b);
    uint32_t u;
    memcpy(&u, &h, 4);
    return u;
}

// ---------------- prep 1: per-node exponentials ----------------
__global__ void prep_stats(const float* __restrict__ nodes, const float* __restrict__ a) {
    int gw = blockIdx.x * 8 + (threadIdx.x >> 5);
    int lane = threadIdx.x & 31;
    float4 x = *(const float4*)(nodes + (size_t)gw * DIM + lane * 4);
    float4 w1 = *(const float4*)(a + lane * 4);
    float4 w2 = *(const float4*)(a + DIM + lane * 4);
    float v1 = x.x * w1.x + x.y * w1.y + x.z * w1.z + x.w * w1.w;
    float v2 = x.x * w2.x + x.y * w2.y + x.z * w2.z + x.w * w2.w;
    #pragma unroll
    for (int o = 16; o; o >>= 1) {
        v1 += __shfl_xor_sync(0xFFFFFFFFu, v1, o);
        v2 += __shfl_xor_sync(0xFFFFFFFFu, v2, o);
    }
    if (lane == 0) {
        g_E1F1[gw] = make_float2(0.0625f * expf(v1), 0.0625f * expf(0.2f * v1));
        g_W2[gw] = make_float2(expf(v2), expf(0.2f * v2));
    }
}

// ---------------- prep 2: fp16 B tiles (KCHUNK=64), padded k-major ----------------
__global__ void prep_b(const float* __restrict__ nodes) {
    int id = blockIdx.x * 256 + threadIdx.x;   // NN*16 threads
    int ng = id & 15;
    int k = id >> 4;
    const float4* src = (const float4*)(nodes + (size_t)k * DIM + ng * 8);
    float4 x = src[0], y = src[1];
    uint4 u;
    u.x = pack_h2(x.x, x.y); u.y = pack_h2(x.z, x.w);
    u.z = pack_h2(y.x, y.y); u.w = pack_h2(y.z, y.w);
    int t = k >> 6, kk = k & 63;
    __half* dst = g_Bt + (size_t)t * (KCHUNK * TILE_STRIDE_H) + kk * TILE_STRIDE_H + ng * 8;
    *(uint4*)dst = u;
}

// ---------------- main kernel: 16 warps, 4-way K split, KCHUNK=64 ----------------
__global__ void __launch_bounds__(TPB, 1)
gat_main(const float* __restrict__ dist, float* __restrict__ out) {
    extern __shared__ char smem[];
    uint32_t sb = smem_u32(smem);
    int tid = threadIdx.x;
    int lane = tid & 31;
    int qtr = tid >> 7;                // 0..3 : k-quarter
    int q = tid & 127;                 // index within quarter
    int wi = (tid >> 5) & 3;           // M-warp within quarter
    int g = lane >> 2, c = lane & 3;
    int row0 = blockIdx.x * MTILE + wi * 16 + g;   // + 8 for second row
    int kq0 = qtr * (NN / 4);          // quarter k-base
    int tile0 = qtr * QITER;           // first B tile of quarter
    uint32_t ring = sb + qtr * RING_BYTES;
    int barid = 1 + qtr;

    // ---- prologue: first two B stages for this quarter ----
    #pragma unroll
    for (int s = 0; s < 2; s++) {
        const char* srcs = (const char*)g_Bt + (size_t)(tile0 + s) * TILE_BYTES;
        #pragma unroll
        for (int i = 0; i < 9; i++) {
            int off = q * 16 + i * (128 * 16);
            if (off < TILE_BYTES) cp16(ring + s * TILE_BYTES + off, srcs + off);
        }
        CP_COMMIT();
    }

    float2 ef0 = g_E1F1[row0];
    float2 ef1 = g_E1F1[row0 + 8];
    const float* dp0 = dist + (size_t)row0 * NN + 2 * c;
    const float* dp1 = dist + (size_t)(row0 + 8) * NN + 2 * c;

    float acc[16][4];
    #pragma unroll
    for (int p = 0; p < 16; p++)
        #pragma unroll
        for (int v = 0; v < 4; v++) acc[p][v] = 0.0f;
    float dn0 = 0.0f, dn1 = 0.0f;

    // dist registers for first chunk of this quarter
    float2 Da[4], Db[4], Dc[4], Dd[4];
    #pragma unroll
    for (int ks = 0; ks < 4; ks++) {
        int k = kq0 + ks * 16;
        Da[ks] = __ldcs((const float2*)(dp0 + k));
        Db[ks] = __ldcs((const float2*)(dp0 + k + 8));
        Dc[ks] = __ldcs((const float2*)(dp1 + k));
        Dd[ks] = __ldcs((const float2*)(dp1 + k + 8));
    }

    int m = lane >> 3, r = lane & 7;
    uint32_t lbase = ((m & 1) * 8 + r) * (TILE_STRIDE_H * 2) + ((m >> 1) * 8) * 2;

    int stg = 0;                       // ring slot of current chunk
    for (int tt = 0; tt < QITER; tt++) {
        int kb = kq0 + tt * KCHUNK;
        CP_WAIT1();
        asm volatile("bar.sync %0, 128;" :: "r"(barid) : "memory");

        // issue B stage tt+2 for this quarter (slot reused from tt-1)
        if (tt + 2 < QITER) {
            const char* srcs = (const char*)g_Bt + (size_t)(tile0 + tt + 2) * TILE_BYTES;
            int slot = stg + 2;
            if (slot >= RING_STAGES) slot -= RING_STAGES;
            uint32_t dsts = ring + slot * TILE_BYTES;
            #pragma unroll
            for (int i = 0; i < 9; i++) {
                int off = q * 16 + i * (128 * 16);
                if (off < TILE_BYTES) cp16(dsts + off, srcs + off);
            }
        }
        CP_COMMIT();

        // ---- build A fragments for this chunk (W2 via read-only gmem, L1-hot) ----
        uint32_t ah[4][4];
        #pragma unroll
        for (int ks = 0; ks < 4; ks++) {
            int kg = kb + ks * 16 + 2 * c;
            float4 Wa = __ldg((const float4*)(g_W2 + kg));
            float4 Wb = __ldg((const float4*)(g_W2 + kg + 8));
            float w00 = (Da[ks].x < 0.5f) ? fmaxf(ef0.x * Wa.x, ef0.y * Wa.y) : 0.0f;
            float w01 = (Da[ks].y < 0.5f) ? fmaxf(ef0.x * Wa.z, ef0.y * Wa.w) : 0.0f;
            float w02 = (Db[ks].x < 0.5f) ? fmaxf(ef0.x * Wb.x, ef0.y * Wb.y) : 0.0f;
            float w03 = (Db[ks].y < 0.5f) ? fmaxf(ef0.x * Wb.z, ef0.y * Wb.w) : 0.0f;
            float w10 = (Dc[ks].x < 0.5f) ? fmaxf(ef1.x * Wa.x, ef1.y * Wa.y) : 0.0f;
            float w11 = (Dc[ks].y < 0.5f) ? fmaxf(ef1.x * Wa.z, ef1.y * Wa.w) : 0.0f;
            float w12 = (Dd[ks].x < 0.5f) ? fmaxf(ef1.x * Wb.x, ef1.y * Wb.y) : 0.0f;
            float w13 = (Dd[ks].y < 0.5f) ? fmaxf(ef1.x * Wb.z, ef1.y * Wb.w) : 0.0f;
            dn0 += (w00 + w01) + (w02 + w03);
            dn1 += (w10 + w11) + (w12 + w13);
            ah[ks][0] = pack_h2(w00, w01);
            ah[ks][1] = pack_h2(w10, w11);
            ah[ks][2] = pack_h2(w02, w03);
            ah[ks][3] = pack_h2(w12, w13);
        }

        // ---- prefetch dist for chunk tt+1 ----
        if (tt + 1 < QITER) {
            #pragma unroll
            for (int ks = 0; ks < 4; ks++) {
                int k = kb + KCHUNK + ks * 16;
                Da[ks] = __ldcs((const float2*)(dp0 + k));
                Db[ks] = __ldcs((const float2*)(dp0 + k + 8));
                Dc[ks] = __ldcs((const float2*)(dp1 + k));
                Dd[ks] = __ldcs((const float2*)(dp1 + k + 8));
            }
        }

        // ---- MMA over 128 feature columns ----
        uint32_t bs = ring + stg * TILE_BYTES + lbase;
        #pragma unroll
        for (int ks = 0; ks < 4; ks++) {
            #pragma unroll
            for (int p = 0; p < 8; p++) {
                uint32_t b0, b1, b2, b3;
                ldm4t(b0, b1, b2, b3, bs + ks * (16 * TILE_STRIDE_H * 2) + p * 32);
                mma16816(acc[2 * p], ah[ks], b0, b1);
                mma16816(acc[2 * p + 1], ah[ks], b2, b3);
            }
        }
        if (++stg == RING_STAGES) stg = 0;
    }

    // ---- epilogue: combine quarters via smem, normalize, store ----
    CP_WAIT0();
    __syncthreads();
    float* red = (float*)smem;    // 3 quarters * 128 threads * 68 floats = 104448 B
    if (qtr != 0) {
        float* rr = red + ((qtr - 1) * 128 + q) * 68;
        #pragma unroll
        for (int p = 0; p < 16; p++)
            *(float4*)(rr + p * 4) = make_float4(acc[p][0], acc[p][1], acc[p][2], acc[p][3]);
        rr[64] = dn0;
        rr[65] = dn1;
    }
    __syncthreads();
    if (qtr == 0) {
        #pragma unroll
        for (int s = 0; s < 3; s++) {
            const float* rr = red + (s * 128 + q) * 68;
            #pragma unroll
            for (int p = 0; p < 16; p++) {
                float4 o = *(const float4*)(rr + p * 4);
                acc[p][0] += o.x; acc[p][1] += o.y; acc[p][2] += o.z; acc[p][3] += o.w;
            }
            dn0 += rr[64];
            dn1 += rr[65];
        }
        dn0 += __shfl_xor_sync(0xFFFFFFFFu, dn0, 1);
        dn0 += __shfl_xor_sync(0xFFFFFFFFu, dn0, 2);
        dn1 += __shfl_xor_sync(0xFFFFFFFFu, dn1, 1);
        dn1 += __shfl_xor_sync(0xFFFFFFFFu, dn1, 2);
        float inv0 = 1.0f / dn0;
        float inv1 = 1.0f / dn1;
        float* o0 = out + (size_t)row0 * DIM + 2 * c;
        float* o1 = out + (size_t)(row0 + 8) * DIM + 2 * c;
        #pragma unroll
        for (int p = 0; p < 16; p++) {
            *(float2*)(o0 + p * 8) = make_float2(acc[p][0] * inv0, acc[p][1] * inv0);
            *(float2*)(o1 + p * 8) = make_float2(acc[p][2] * inv1, acc[p][3] * inv1);
        }
    }
}

extern "C" void kernel_launch(void* const* d_in, const int* in_sizes, int n_in,
                              void* d_out, int out_size) {
    const float* nodes = nullptr;
    const float* dist = nullptr;
    const float* a = nullptr;
    for (int i = 0; i < n_in; i++) {
        if (in_sizes[i] == NN * NN) dist = (const float*)d_in[i];
        else if (in_sizes[i] == NN * DIM) nodes = (const float*)d_in[i];
        else if (in_sizes[i] == 2 * DIM) a = (const float*)d_in[i];
    }
    float* out = (float*)d_out;

    static bool attr_set = false;
    if (!attr_set) {
        cudaFuncSetAttribute(gat_main, cudaFuncAttributeMaxDynamicSharedMemorySize, SMEM_TOTAL);
        attr_set = true;
    }

    prep_stats<<<NN / 8, 256>>>(nodes, a);
    prep_b<<<(NN * 16) / 256, 256>>>(nodes);
    gat_main<<<NN / MTILE, TPB, SMEM_TOTAL>>>(dist, out);
}

// round 13
// speedup vs baseline: 1.2690x; 1.2690x over previous
#include <cuda_runtime.h>
#include <cuda_fp16.h>
#include <cstdint>
#include <cstring>

#define NN 8192
#define DIM 128
#define KCHUNK 64
#define NITER (NN / KCHUNK)            // 128
#define HITER (NITER / 2)              // 64 chunks per half
#define MTILE 64
#define TPB 256
#define TILE_STRIDE_H 136              // halves per k-row (128 + 8 pad) -> 272 B
#define TILE_BYTES (KCHUNK * TILE_STRIDE_H * 2)   // 17408
#define RING_BYTES (4 * TILE_BYTES)    // per-half ring
#define W2_OFF (8 * TILE_BYTES)        // 139264
#define SMEM_TOTAL (W2_OFF + NN * 8)   // 204800

__device__ float2 g_W2[NN];            // (exp(s2), exp(0.2 s2))
__device__ float2 g_E1F1[NN];          // 0.0625 * (exp(s1), exp(0.2 s1))
__device__ __align__(16) __half g_Bt[NITER * KCHUNK * TILE_STRIDE_H];

// ---------------- helpers ----------------
__device__ __forceinline__ uint32_t smem_u32(const void* p) {
    uint32_t r;
    asm("{ .reg .u64 t; cvta.to.shared.u64 t, %1; cvt.u32.u64 %0, t; }" : "=r"(r) : "l"(p));
    return r;
}
__device__ __forceinline__ void cp16(uint32_t d, const void* s) {
    asm volatile("cp.async.cg.shared.global [%0], [%1], 16;" :: "r"(d), "l"(s) : "memory");
}
#define CP_COMMIT() asm volatile("cp.async.commit_group;" ::: "memory")
#define CP_WAIT2() asm volatile("cp.async.wait_group 2;" ::: "memory")
#define CP_WAIT3() asm volatile("cp.async.wait_group 3;" ::: "memory")
#define CP_WAIT0() asm volatile("cp.async.wait_group 0;" ::: "memory")

__device__ __forceinline__ void ldm4t(uint32_t& r0, uint32_t& r1, uint32_t& r2, uint32_t& r3, uint32_t a) {
    asm volatile("ldmatrix.sync.aligned.m8n8.x4.trans.shared.b16 {%0,%1,%2,%3}, [%4];"
        : "=r"(r0), "=r"(r1), "=r"(r2), "=r"(r3) : "r"(a));
}
__device__ __forceinline__ void mma16816(float* d, const uint32_t* a, uint32_t b0, uint32_t b1) {
    asm volatile("mma.sync.aligned.m16n8k16.row.col.f32.f16.f16.f32 "
        "{%0,%1,%2,%3},{%4,%5,%6,%7},{%8,%9},{%0,%1,%2,%3};"
        : "+f"(d[0]), "+f"(d[1]), "+f"(d[2]), "+f"(d[3])
        : "r"(a[0]), "r"(a[1]), "r"(a[2]), "r"(a[3]), "r"(b0), "r"(b1));
}
__device__ __forceinline__ uint32_t pack_h2(float a, float b) {
    __half2 h = __floats2half2_rn(a, b);
    uint32_t u;
    memcpy(&u, &h, 4);
    return u;
}

// ---------------- prep 1: per-node exponentials ----------------
__global__ void prep_stats(const float* __restrict__ nodes, const float* __restrict__ a) {
    int gw = blockIdx.x * 8 + (threadIdx.x >> 5);
    int lane = threadIdx.x & 31;
    float4 x = *(const float4*)(nodes + (size_t)gw * DIM + lane * 4);
    float4 w1 = *(const float4*)(a + lane * 4);
    float4 w2 = *(const float4*)(a + DIM + lane * 4);
    float v1 = x.x * w1.x + x.y * w1.y + x.z * w1.z + x.w * w1.w;
    float v2 = x.x * w2.x + x.y * w2.y + x.z * w2.z + x.w * w2.w;
    #pragma unroll
    for (int o = 16; o; o >>= 1) {
        v1 += __shfl_xor_sync(0xFFFFFFFFu, v1, o);
        v2 += __shfl_xor_sync(0xFFFFFFFFu, v2, o);
    }
    if (lane == 0) {
        g_E1F1[gw] = make_float2(0.0625f * expf(v1), 0.0625f * expf(0.2f * v1));
        g_W2[gw] = make_float2(expf(v2), expf(0.2f * v2));
    }
}

// ---------------- prep 2: fp16 B tiles, padded k-major layout ----------------
__global__ void prep_b(const float* __restrict__ nodes) {
    int id = blockIdx.x * 256 + threadIdx.x;   // NN*16 threads
    int ng = id & 15;
    int k = id >> 4;
    const float4* src = (const float4*)(nodes + (size_t)k * DIM + ng * 8);
    float4 x = src[0], y = src[1];
    uint4 u;
    u.x = pack_h2(x.x, x.y); u.y = pack_h2(x.z, x.w);
    u.z = pack_h2(y.x, y.y); u.w = pack_h2(y.z, y.w);
    int t = k >> 6, kk = k & 63;
    __half* dst = g_Bt + (size_t)t * (KCHUNK * TILE_STRIDE_H) + kk * TILE_STRIDE_H + ng * 8;
    *(uint4*)dst = u;
}

// ---------------- main kernel: 8 warps, K-split halves, pipelined ldmatrix ----------------
__global__ void __launch_bounds__(TPB, 1)
gat_main(const float* __restrict__ dist, float* __restrict__ out) {
    extern __shared__ char smem[];
    uint32_t sb = smem_u32(smem);
    int tid = threadIdx.x;
    int lane = tid & 31;
    int half = tid >> 7;               // 0: chunks 0..63, 1: chunks 64..127
    int q = tid & 127;                 // index within half
    int wi = (tid >> 5) & 3;           // warp-in-half
    int g = lane >> 2, c = lane & 3;
    int row0 = blockIdx.x * MTILE + wi * 16 + g;   // + 8 for second row
    int t0 = half * HITER;
    uint32_t ring = sb + half * RING_BYTES;
    int barid = 1 + half;

    // ---- prologue ----
    // G0: this thread's share of W2 (all 256 threads cover 64 KB)
    #pragma unroll
    for (int i = 0; i < 16; i++)
        cp16(sb + W2_OFF + (tid + i * TPB) * 16, (const char*)g_W2 + (tid + i * TPB) * 16);
    CP_COMMIT();
    // G1..G3: first three B stages for this half (128 threads each)
    #pragma unroll
    for (int s = 0; s < 3; s++) {
        const char* srcs = (const char*)g_Bt + (size_t)(t0 + s) * TILE_BYTES;
        #pragma unroll
        for (int i = 0; i < 9; i++) {
            int off = q * 16 + i * (128 * 16);
            if (off < TILE_BYTES) cp16(ring + s * TILE_BYTES + off, srcs + off);
        }
        CP_COMMIT();
    }
    CP_WAIT3();          // W2 (G0) complete for this thread
    __syncthreads();     // W2 visible block-wide

    float2 ef0 = g_E1F1[row0];
    float2 ef1 = g_E1F1[row0 + 8];
    const float* dp0 = dist + (size_t)row0 * NN + 2 * c;
    const float* dp1 = dist + (size_t)(row0 + 8) * NN + 2 * c;

    float acc[16][4];
    #pragma unroll
    for (int p = 0; p < 16; p++)
        #pragma unroll
        for (int v = 0; v < 4; v++) acc[p][v] = 0.0f;
    float dn0 = 0.0f, dn1 = 0.0f;

    // dist registers for first chunk of this half
    float2 Da[4], Db[4], Dc[4], Dd[4];
    #pragma unroll
    for (int ks = 0; ks < 4; ks++) {
        int k = t0 * KCHUNK + ks * 16;
        Da[ks] = __ldcs((const float2*)(dp0 + k));
        Db[ks] = __ldcs((const float2*)(dp0 + k + 8));
        Dc[ks] = __ldcs((const float2*)(dp1 + k));
        Dd[ks] = __ldcs((const float2*)(dp1 + k + 8));
    }

    int m = lane >> 3, r = lane & 7;
    uint32_t lbase = ((m & 1) * 8 + r) * (TILE_STRIDE_H * 2) + ((m >> 1) * 8) * 2;

    for (int tt = 0; tt < HITER; tt++) {
        int t = t0 + tt;
        CP_WAIT2();
        asm volatile("bar.sync %0, 128;" :: "r"(barid) : "memory");

        uint32_t bs = ring + (tt & 3) * TILE_BYTES + lbase;
        #define BADDR(s) (bs + ((s) >> 3) * (16 * TILE_STRIDE_H * 2) + ((s) & 7) * 32)

        // issue the first two B-fragment loads now; latency hides under A-build
        uint32_t b0, b1, b2, b3, e0, e1, e2, e3;
        ldm4t(b0, b1, b2, b3, BADDR(0));
        ldm4t(e0, e1, e2, e3, BADDR(1));

        // issue next B stage (or empty group)
        if (tt + 3 < HITER) {
            const char* srcs = (const char*)g_Bt + (size_t)(t + 3) * TILE_BYTES;
            uint32_t dsts = ring + ((tt + 3) & 3) * TILE_BYTES;
            #pragma unroll
            for (int i = 0; i < 9; i++) {
                int off = q * 16 + i * (128 * 16);
                if (off < TILE_BYTES) cp16(dsts + off, srcs + off);
            }
        }
        CP_COMMIT();

        // ---- build A fragments for chunk t (hides the two ldmatrix above) ----
        uint32_t ah[4][4];
        #pragma unroll
        for (int ks = 0; ks < 4; ks++) {
            int kg = t * KCHUNK + ks * 16 + 2 * c;
            float4 Wa = *(const float4*)(smem + W2_OFF + kg * 8);
            float4 Wb = *(const float4*)(smem + W2_OFF + (kg + 8) * 8);
            float w00 = (Da[ks].x < 0.5f) ? fmaxf(ef0.x * Wa.x, ef0.y * Wa.y) : 0.0f;
            float w01 = (Da[ks].y < 0.5f) ? fmaxf(ef0.x * Wa.z, ef0.y * Wa.w) : 0.0f;
            float w02 = (Db[ks].x < 0.5f) ? fmaxf(ef0.x * Wb.x, ef0.y * Wb.y) : 0.0f;
            float w03 = (Db[ks].y < 0.5f) ? fmaxf(ef0.x * Wb.z, ef0.y * Wb.w) : 0.0f;
            float w10 = (Dc[ks].x < 0.5f) ? fmaxf(ef1.x * Wa.x, ef1.y * Wa.y) : 0.0f;
            float w11 = (Dc[ks].y < 0.5f) ? fmaxf(ef1.x * Wa.z, ef1.y * Wa.w) : 0.0f;
            float w12 = (Dd[ks].x < 0.5f) ? fmaxf(ef1.x * Wb.x, ef1.y * Wb.y) : 0.0f;
            float w13 = (Dd[ks].y < 0.5f) ? fmaxf(ef1.x * Wb.z, ef1.y * Wb.w) : 0.0f;
            dn0 += (w00 + w01) + (w02 + w03);
            dn1 += (w10 + w11) + (w12 + w13);
            ah[ks][0] = pack_h2(w00, w01);
            ah[ks][1] = pack_h2(w10, w11);
            ah[ks][2] = pack_h2(w02, w03);
            ah[ks][3] = pack_h2(w12, w13);
        }

        // ---- prefetch dist for chunk t+1 ----
        if (tt + 1 < HITER) {
            #pragma unroll
            for (int ks = 0; ks < 4; ks++) {
                int k = (t + 1) * KCHUNK + ks * 16;
                Da[ks] = __ldcs((const float2*)(dp0 + k));
                Db[ks] = __ldcs((const float2*)(dp0 + k + 8));
                Dc[ks] = __ldcs((const float2*)(dp1 + k));
                Dd[ks] = __ldcs((const float2*)(dp1 + k + 8));
            }
        }

        // ---- MMA: 32 steps, B frags double-buffered two steps ahead ----
        #pragma unroll
        for (int s = 0; s < 32; s += 2) {
            int p0 = s & 7;
            mma16816(acc[2 * p0], ah[s >> 3], b0, b1);
            mma16816(acc[2 * p0 + 1], ah[s >> 3], b2, b3);
            if (s + 2 < 32) ldm4t(b0, b1, b2, b3, BADDR(s + 2));
            int p1 = (s + 1) & 7;
            mma16816(acc[2 * p1], ah[(s + 1) >> 3], e0, e1);
            mma16816(acc[2 * p1 + 1], ah[(s + 1) >> 3], e2, e3);
            if (s + 3 < 32) ldm4t(e0, e1, e2, e3, BADDR(s + 3));
        }
        #undef BADDR
    }

    // ---- epilogue: combine halves via smem, normalize, store ----
    CP_WAIT0();
    __syncthreads();
    float* red = (float*)smem;    // reuse ring area: 128 threads * 68 floats
    if (half == 1) {
        float* rr = red + q * 68;
        #pragma unroll
        for (int p = 0; p < 16; p++)
            *(float4*)(rr + p * 4) = make_float4(acc[p][0], acc[p][1], acc[p][2], acc[p][3]);
        rr[64] = dn0;
        rr[65] = dn1;
    }
    __syncthreads();
    if (half == 0) {
        const float* rr = red + q * 68;
        #pragma unroll
        for (int p = 0; p < 16; p++) {
            float4 o = *(const float4*)(rr + p * 4);
            acc[p][0] += o.x; acc[p][1] += o.y; acc[p][2] += o.z; acc[p][3] += o.w;
        }
        dn0 += rr[64];
        dn1 += rr[65];
        dn0 += __shfl_xor_sync(0xFFFFFFFFu, dn0, 1);
        dn0 += __shfl_xor_sync(0xFFFFFFFFu, dn0, 2);
        dn1 += __shfl_xor_sync(0xFFFFFFFFu, dn1, 1);
        dn1 += __shfl_xor_sync(0xFFFFFFFFu, dn1, 2);
        float inv0 = 1.0f / dn0;
        float inv1 = 1.0f / dn1;
        float* o0 = out + (size_t)row0 * DIM + 2 * c;
        float* o1 = out + (size_t)(row0 + 8) * DIM + 2 * c;
        #pragma unroll
        for (int p = 0; p < 16; p++) {
            *(float2*)(o0 + p * 8) = make_float2(acc[p][0] * inv0, acc[p][1] * inv0);
            *(float2*)(o1 + p * 8) = make_float2(acc[p][2] * inv1, acc[p][3] * inv1);
        }
    }
}

extern "C" void kernel_launch(void* const* d_in, const int* in_sizes, int n_in,
                              void* d_out, int out_size) {
    const float* nodes = nullptr;
    const float* dist = nullptr;
    const float* a = nullptr;
    for (int i = 0; i < n_in; i++) {
        if (in_sizes[i] == NN * NN) dist = (const float*)d_in[i];
        else if (in_sizes[i] == NN * DIM) nodes = (const float*)d_in[i];
        else if (in_sizes[i] == 2 * DIM) a = (const float*)d_in[i];
    }
    float* out = (float*)d_out;

    static bool attr_set = false;
    if (!attr_set) {
        cudaFuncSetAttribute(gat_main, cudaFuncAttributeMaxDynamicSharedMemorySize, SMEM_TOTAL);
        attr_set = true;
    }

    prep_stats<<<NN / 8, 256>>>(nodes, a);
    prep_b<<<(NN * 16) / 256, 256>>>(nodes);
    gat_main<<<NN / MTILE, TPB, SMEM_TOTAL>>>(dist, out);
}

// round 14
// speedup vs baseline: 1.4055x; 1.1076x over previous
#include <cuda_runtime.h>
#include <cuda_fp16.h>
#include <cstdint>
#include <cstring>

#define NN 8192
#define DIM 128
#define KCHUNK 64
#define NITER (NN / KCHUNK)            // 128
#define HITER (NITER / 2)              // 64 chunks per half
#define MTILE 64
#define TPB 256
#define TILE_STRIDE_H 136              // halves per k-row (128 + 8 pad) -> 272 B
#define TILE_BYTES (KCHUNK * TILE_STRIDE_H * 2)   // 17408
#define RING_BYTES (4 * TILE_BYTES)    // per-half ring
#define W2_OFF (8 * TILE_BYTES)        // 139264
#define SMEM_TOTAL (W2_OFF + NN * 8)   // 204800
#define WSCALE 0.015625f

__device__ float2 g_W2[NN];            // (exp(s2), exp(0.2 s2))
__device__ float2 g_E1F1[NN];          // WSCALE * (exp(s1), exp(0.2 s1))
__device__ __align__(16) __half g_Bt[NITER * KCHUNK * TILE_STRIDE_H];

// ---------------- helpers ----------------
__device__ __forceinline__ uint32_t smem_u32(const void* p) {
    uint32_t r;
    asm("{ .reg .u64 t; cvta.to.shared.u64 t, %1; cvt.u32.u64 %0, t; }" : "=r"(r) : "l"(p));
    return r;
}
__device__ __forceinline__ void cp16(uint32_t d, const void* s) {
    asm volatile("cp.async.cg.shared.global [%0], [%1], 16;" :: "r"(d), "l"(s) : "memory");
}
#define CP_COMMIT() asm volatile("cp.async.commit_group;" ::: "memory")
#define CP_WAIT2() asm volatile("cp.async.wait_group 2;" ::: "memory")
#define CP_WAIT3() asm volatile("cp.async.wait_group 3;" ::: "memory")
#define CP_WAIT0() asm volatile("cp.async.wait_group 0;" ::: "memory")

__device__ __forceinline__ void ldm4t(uint32_t& r0, uint32_t& r1, uint32_t& r2, uint32_t& r3, uint32_t a) {
    asm volatile("ldmatrix.sync.aligned.m8n8.x4.trans.shared.b16 {%0,%1,%2,%3}, [%4];"
        : "=r"(r0), "=r"(r1), "=r"(r2), "=r"(r3) : "r"(a));
}
// fp16-accumulate MMA: D (2 regs = 4 halves) += A*B
__device__ __forceinline__ void mma16816h(uint32_t* d, const uint32_t* a, uint32_t b0, uint32_t b1) {
    asm volatile("mma.sync.aligned.m16n8k16.row.col.f16.f16.f16.f16 "
        "{%0,%1},{%2,%3,%4,%5},{%6,%7},{%0,%1};"
        : "+r"(d[0]), "+r"(d[1])
        : "r"(a[0]), "r"(a[1]), "r"(a[2]), "r"(a[3]), "r"(b0), "r"(b1));
}
__device__ __forceinline__ uint32_t pack_h2(float a, float b) {
    __half2 h = __floats2half2_rn(a, b);
    uint32_t u;
    memcpy(&u, &h, 4);
    return u;
}

// ---------------- prep 1: per-node exponentials ----------------
__global__ void prep_stats(const float* __restrict__ nodes, const float* __restrict__ a) {
    int gw = blockIdx.x * 8 + (threadIdx.x >> 5);
    int lane = threadIdx.x & 31;
    float4 x = *(const float4*)(nodes + (size_t)gw * DIM + lane * 4);
    float4 w1 = *(const float4*)(a + lane * 4);
    float4 w2 = *(const float4*)(a + DIM + lane * 4);
    float v1 = x.x * w1.x + x.y * w1.y + x.z * w1.z + x.w * w1.w;
    float v2 = x.x * w2.x + x.y * w2.y + x.z * w2.z + x.w * w2.w;
    #pragma unroll
    for (int o = 16; o; o >>= 1) {
        v1 += __shfl_xor_sync(0xFFFFFFFFu, v1, o);
        v2 += __shfl_xor_sync(0xFFFFFFFFu, v2, o);
    }
    if (lane == 0) {
        g_E1F1[gw] = make_float2(WSCALE * expf(v1), WSCALE * expf(0.2f * v1));
        g_W2[gw] = make_float2(expf(v2), expf(0.2f * v2));
    }
}

// ---------------- prep 2: fp16 B tiles, padded k-major layout ----------------
__global__ void prep_b(const float* __restrict__ nodes) {
    int id = blockIdx.x * 256 + threadIdx.x;   // NN*16 threads
    int ng = id & 15;
    int k = id >> 4;
    const float4* src = (const float4*)(nodes + (size_t)k * DIM + ng * 8);
    float4 x = src[0], y = src[1];
    uint4 u;
    u.x = pack_h2(x.x, x.y); u.y = pack_h2(x.z, x.w);
    u.z = pack_h2(y.x, y.y); u.w = pack_h2(y.z, y.w);
    int t = k >> 6, kk = k & 63;
    __half* dst = g_Bt + (size_t)t * (KCHUNK * TILE_STRIDE_H) + kk * TILE_STRIDE_H + ng * 8;
    *(uint4*)dst = u;
}

// ---------------- main kernel: 8 warps, K-split halves, fp16-acc MMA ----------------
__global__ void __launch_bounds__(TPB, 1)
gat_main(const float* __restrict__ dist, float* __restrict__ out) {
    extern __shared__ char smem[];
    uint32_t sb = smem_u32(smem);
    int tid = threadIdx.x;
    int lane = tid & 31;
    int half = tid >> 7;               // 0: chunks 0..63, 1: chunks 64..127
    int q = tid & 127;                 // index within half
    int wi = (tid >> 5) & 3;           // warp-in-half
    int g = lane >> 2, c = lane & 3;
    int row0 = blockIdx.x * MTILE + wi * 16 + g;   // + 8 for second row
    int t0 = half * HITER;
    uint32_t ring = sb + half * RING_BYTES;
    int barid = 1 + half;

    // ---- prologue ----
    #pragma unroll
    for (int i = 0; i < 16; i++)
        cp16(sb + W2_OFF + (tid + i * TPB) * 16, (const char*)g_W2 + (tid + i * TPB) * 16);
    CP_COMMIT();
    #pragma unroll
    for (int s = 0; s < 3; s++) {
        const char* srcs = (const char*)g_Bt + (size_t)(t0 + s) * TILE_BYTES;
        #pragma unroll
        for (int i = 0; i < 9; i++) {
            int off = q * 16 + i * (128 * 16);
            if (off < TILE_BYTES) cp16(ring + s * TILE_BYTES + off, srcs + off);
        }
        CP_COMMIT();
    }
    CP_WAIT3();          // W2 (G0) complete for this thread
    __syncthreads();     // W2 visible block-wide

    float2 ef0 = g_E1F1[row0];
    float2 ef1 = g_E1F1[row0 + 8];
    const float* dp0 = dist + (size_t)row0 * NN + 2 * c;
    const float* dp1 = dist + (size_t)(row0 + 8) * NN + 2 * c;

    float acc[16][4];
    #pragma unroll
    for (int p = 0; p < 16; p++)
        #pragma unroll
        for (int v = 0; v < 4; v++) acc[p][v] = 0.0f;
    float dn0 = 0.0f, dn1 = 0.0f;

    float2 Da[4], Db[4], Dc[4], Dd[4];
    #pragma unroll
    for (int ks = 0; ks < 4; ks++) {
        int k = t0 * KCHUNK + ks * 16;
        Da[ks] = __ldcs((const float2*)(dp0 + k));
        Db[ks] = __ldcs((const float2*)(dp0 + k + 8));
        Dc[ks] = __ldcs((const float2*)(dp1 + k));
        Dd[ks] = __ldcs((const float2*)(dp1 + k + 8));
    }

    int m = lane >> 3, r = lane & 7;
    uint32_t lbase = ((m & 1) * 8 + r) * (TILE_STRIDE_H * 2) + ((m >> 1) * 8) * 2;

    for (int tt = 0; tt < HITER; tt++) {
        int t = t0 + tt;
        CP_WAIT2();
        asm volatile("bar.sync %0, 128;" :: "r"(barid) : "memory");

        // issue next B stage (or empty group)
        if (tt + 3 < HITER) {
            const char* srcs = (const char*)g_Bt + (size_t)(t + 3) * TILE_BYTES;
            uint32_t dsts = ring + ((tt + 3) & 3) * TILE_BYTES;
            #pragma unroll
            for (int i = 0; i < 9; i++) {
                int off = q * 16 + i * (128 * 16);
                if (off < TILE_BYTES) cp16(dsts + off, srcs + off);
            }
        }
        CP_COMMIT();

        // ---- build A fragments for chunk t ----
        uint32_t ah[4][4];
        #pragma unroll
        for (int ks = 0; ks < 4; ks++) {
            int kg = t * KCHUNK + ks * 16 + 2 * c;
            float4 Wa = *(const float4*)(smem + W2_OFF + kg * 8);
            float4 Wb = *(const float4*)(smem + W2_OFF + (kg + 8) * 8);
            float w00 = (Da[ks].x < 0.5f) ? fmaxf(ef0.x * Wa.x, ef0.y * Wa.y) : 0.0f;
            float w01 = (Da[ks].y < 0.5f) ? fmaxf(ef0.x * Wa.z, ef0.y * Wa.w) : 0.0f;
            float w02 = (Db[ks].x < 0.5f) ? fmaxf(ef0.x * Wb.x, ef0.y * Wb.y) : 0.0f;
            float w03 = (Db[ks].y < 0.5f) ? fmaxf(ef0.x * Wb.z, ef0.y * Wb.w) : 0.0f;
            float w10 = (Dc[ks].x < 0.5f) ? fmaxf(ef1.x * Wa.x, ef1.y * Wa.y) : 0.0f;
            float w11 = (Dc[ks].y < 0.5f) ? fmaxf(ef1.x * Wa.z, ef1.y * Wa.w) : 0.0f;
            float w12 = (Dd[ks].x < 0.5f) ? fmaxf(ef1.x * Wb.x, ef1.y * Wb.y) : 0.0f;
            float w13 = (Dd[ks].y < 0.5f) ? fmaxf(ef1.x * Wb.z, ef1.y * Wb.w) : 0.0f;
            dn0 += (w00 + w01) + (w02 + w03);
            dn1 += (w10 + w11) + (w12 + w13);
            ah[ks][0] = pack_h2(w00, w01);
            ah[ks][1] = pack_h2(w10, w11);
            ah[ks][2] = pack_h2(w02, w03);
            ah[ks][3] = pack_h2(w12, w13);
        }

        // ---- prefetch dist for chunk t+1 ----
        if (tt + 1 < HITER) {
            #pragma unroll
            for (int ks = 0; ks < 4; ks++) {
                int k = (t + 1) * KCHUNK + ks * 16;
                Da[ks] = __ldcs((const float2*)(dp0 + k));
                Db[ks] = __ldcs((const float2*)(dp0 + k + 8));
                Dc[ks] = __ldcs((const float2*)(dp1 + k));
                Dd[ks] = __ldcs((const float2*)(dp1 + k + 8));
            }
        }

        // ---- MMA (fp16 accumulate within chunk) ----
        uint32_t hacc[16][2];
        #pragma unroll
        for (int p = 0; p < 16; p++) { hacc[p][0] = 0u; hacc[p][1] = 0u; }

        uint32_t bs = ring + (tt & 3) * TILE_BYTES + lbase;
        #pragma unroll
        for (int ks = 0; ks < 4; ks++) {
            #pragma unroll
            for (int p = 0; p < 8; p++) {
                uint32_t b0, b1, b2, b3;
                ldm4t(b0, b1, b2, b3, bs + ks * (16 * TILE_STRIDE_H * 2) + p * 32);
                mma16816h(hacc[2 * p], ah[ks], b0, b1);
                mma16816h(hacc[2 * p + 1], ah[ks], b2, b3);
            }
        }

        // ---- promote chunk partials to fp32 master accumulators ----
        #pragma unroll
        for (int p = 0; p < 16; p++) {
            __half2 h0, h1;
            memcpy(&h0, &hacc[p][0], 4);
            memcpy(&h1, &hacc[p][1], 4);
            float2 lo = __half22float2(h0);
            float2 hi = __half22float2(h1);
            acc[p][0] += lo.x; acc[p][1] += lo.y;
            acc[p][2] += hi.x; acc[p][3] += hi.y;
        }
    }

    // ---- epilogue: combine halves via smem, normalize, store ----
    CP_WAIT0();
    __syncthreads();
    float* red = (float*)smem;    // reuse ring area: 128 threads * 68 floats
    if (half == 1) {
        float* rr = red + q * 68;
        #pragma unroll
        for (int p = 0; p < 16; p++)
            *(float4*)(rr + p * 4) = make_float4(acc[p][0], acc[p][1], acc[p][2], acc[p][3]);
        rr[64] = dn0;
        rr[65] = dn1;
    }
    __syncthreads();
    if (half == 0) {
        const float* rr = red + q * 68;
        #pragma unroll
        for (int p = 0; p < 16; p++) {
            float4 o = *(const float4*)(rr + p * 4);
            acc[p][0] += o.x; acc[p][1] += o.y; acc[p][2] += o.z; acc[p][3] += o.w;
        }
        dn0 += rr[64];
        dn1 += rr[65];
        dn0 += __shfl_xor_sync(0xFFFFFFFFu, dn0, 1);
        dn0 += __shfl_xor_sync(0xFFFFFFFFu, dn0, 2);
        dn1 += __shfl_xor_sync(0xFFFFFFFFu, dn1, 1);
        dn1 += __shfl_xor_sync(0xFFFFFFFFu, dn1, 2);
        float inv0 = 1.0f / dn0;
        float inv1 = 1.0f / dn1;
        float* o0 = out + (size_t)row0 * DIM + 2 * c;
        float* o1 = out + (size_t)(row0 + 8) * DIM + 2 * c;
        #pragma unroll
        for (int p = 0; p < 16; p++) {
            *(float2*)(o0 + p * 8) = make_float2(acc[p][0] * inv0, acc[p][1] * inv0);
            *(float2*)(o1 + p * 8) = make_float2(acc[p][2] * inv1, acc[p][3] * inv1);
        }
    }
}

extern "C" void kernel_launch(void* const* d_in, const int* in_sizes, int n_in,
                              void* d_out, int out_size) {
    const float* nodes = nullptr;
    const float* dist = nullptr;
    const float* a = nullptr;
    for (int i = 0; i < n_in; i++) {
        if (in_sizes[i] == NN * NN) dist = (const float*)d_in[i];
        else if (in_sizes[i] == NN * DIM) nodes = (const float*)d_in[i];
        else if (in_sizes[i] == 2 * DIM) a = (const float*)d_in[i];
    }
    float* out = (float*)d_out;

    static bool attr_set = false;
    if (!attr_set) {
        cudaFuncSetAttribute(gat_main, cudaFuncAttributeMaxDynamicSharedMemorySize, SMEM_TOTAL);
        attr_set = true;
    }

    prep_stats<<<NN / 8, 256>>>(nodes, a);
    prep_b<<<(NN * 16) / 256, 256>>>(nodes);
    gat_main<<<NN / MTILE, TPB, SMEM_TOTAL>>>(dist, out);
}